// round 9
// baseline (speedup 1.0000x reference)
#include <cuda_runtime.h>
#include <mma.h>
#include <math.h>

using namespace nvcuda;

#define B_    2
#define QLEN  1024
#define MLEN  1024
#define KLEN  2048
#define E_    1024
#define H_    16
#define DH_   64
#define HD_   1024
#define FF_   4096

// ---------------- scratch (device globals: allocation-free) ----------------
__device__ float g_cat [(size_t)B_*KLEN*E_];
__device__ float g_q   [(size_t)B_*QLEN*HD_];
__device__ float g_qw  [(size_t)B_*QLEN*HD_];
__device__ float g_qr  [(size_t)B_*QLEN*HD_];
__device__ float g_k   [(size_t)B_*KLEN*HD_];
__device__ float g_v   [(size_t)B_*KLEN*HD_];
__device__ float g_rp  [(size_t)KLEN*HD_];
__device__ float g_bd  [(size_t)B_*H_*QLEN*KLEN];     // BD_raw (256MB)
__device__ float g_o   [(size_t)B_*QLEN*HD_];
__device__ float g_x   [(size_t)B_*QLEN*E_];
__device__ float g_h1  [(size_t)B_*QLEN*FF_];
__device__ float g_y   [(size_t)B_*QLEN*E_];
__device__ float g_y2  [(size_t)B_*QLEN*E_];

// ---------------- helpers ----------------
__device__ __forceinline__ void cpa16(float* dst, const float* src) {
    unsigned d = (unsigned)__cvta_generic_to_shared(dst);
    asm volatile("cp.async.cg.shared.global [%0], [%1], 16;\n" :: "r"(d), "l"(src));
}
__device__ __forceinline__ void cpa_commit() { asm volatile("cp.async.commit_group;\n"); }

// ---------------- small elementwise kernels ----------------
__global__ void concat_kernel(const float4* __restrict__ member,
                              const float4* __restrict__ w,
                              float4* __restrict__ cat)
{
    int idx = blockIdx.x * 256 + threadIdx.x;
    const int per_b = (KLEN * E_) / 4;
    const int half  = (MLEN * E_) / 4;
    int b = idx / per_b;
    int r = idx - b * per_b;
    cat[idx] = (r < half) ? member[b * half + r] : w[b * half + (r - half)];
}

__global__ void bias_add2_kernel(const float* __restrict__ q,
                                 const float* __restrict__ b1,
                                 const float* __restrict__ b2,
                                 float* __restrict__ o1,
                                 float* __restrict__ o2, int n)
{
    int i = blockIdx.x * 256 + threadIdx.x;
    if (i < n) {
        float v = q[i];
        int c = i & (HD_ - 1);
        o1[i] = v + b1[c];
        o2[i] = v + b2[c];
    }
}

// ---------------- multi-stage cp.async tf32 WMMA GEMM (NN/NT) ----------------
template<int BM, int BN, int BK, int WM, int WN, int NWARP, int NSTG, int NT, int RELU>
__global__ void __launch_bounds__(NWARP*32, 2) gemm4(
    const float* __restrict__ Ag, const float* __restrict__ Bg, float* __restrict__ Cg,
    int K, int lda, int ldb, int ldc,
    long long sAb, long long sAh, long long sBb, long long sBh,
    long long sCb, long long sCh, int Hn)
{
    constexpr int NTH  = NWARP * 32;
    constexpr int AL   = BK + 4;
    constexpr int BLnn = BN + 4;
    constexpr int ASZ  = BM * AL;
    constexpr int BSZ  = NT ? BN * AL : BK * BLnn;
    constexpr int STG  = ASZ + BSZ;
    constexpr int FM   = WM / 16;
    constexpr int FN   = WN / 16;
    constexpr int WROWS = BM / WM;

    extern __shared__ float sm[];

    int z = blockIdx.z, bb = z / Hn, hh = z - bb * Hn;
    const float* A  = Ag + (long long)bb * sAb + (long long)hh * sAh
                         + (long long)(blockIdx.y * BM) * lda;
    const float* Bp = Bg + (long long)bb * sBb + (long long)hh * sBh
                         + (NT ? (long long)(blockIdx.x * BN) * ldb
                               : (long long)(blockIdx.x * BN));
    float*       C  = Cg + (long long)bb * sCb + (long long)hh * sCh
                         + (long long)(blockIdx.y * BM) * ldc + blockIdx.x * BN;

    int tid = threadIdx.x;
    int wid = tid >> 5;
    int wm = wid % WROWS, wn = wid / WROWS;

    wmma::fragment<wmma::accumulator, 16, 16, 8, float> acc[FM][FN];
#pragma unroll
    for (int i = 0; i < FM; i++)
#pragma unroll
        for (int j = 0; j < FN; j++) wmma::fill_fragment(acc[i][j], 0.f);

    auto load_tile = [&](int s, int k0) {
        float* Ab = sm + s * STG;
        float* Bb = Ab + ASZ;
#pragma unroll
        for (int c = tid; c < BM * BK / 4; c += NTH) {
            int row = c / (BK / 4), c4 = c % (BK / 4);
            cpa16(&Ab[row * AL + c4 * 4], A + (long long)row * lda + k0 + c4 * 4);
        }
        if (NT) {
#pragma unroll
            for (int c = tid; c < BN * BK / 4; c += NTH) {
                int row = c / (BK / 4), c4 = c % (BK / 4);
                cpa16(&Bb[row * AL + c4 * 4], Bp + (long long)row * ldb + k0 + c4 * 4);
            }
        } else {
#pragma unroll
            for (int c = tid; c < BK * BN / 4; c += NTH) {
                int row = c / (BN / 4), c4 = c % (BN / 4);
                cpa16(&Bb[row * BLnn + c4 * 4], Bp + (long long)(k0 + row) * ldb + c4 * 4);
            }
        }
    };

    int niter = K / BK;
    int pre = (niter < NSTG - 1) ? niter : NSTG - 1;
    for (int s = 0; s < pre; ++s) { load_tile(s, s * BK); cpa_commit(); }

    for (int it = 0; it < niter; ++it) {
        asm volatile("cp.async.wait_group %0;\n" :: "n"(NSTG - 2));
        __syncthreads();
        int nx = it + NSTG - 1;
        if (nx < niter) load_tile(nx % NSTG, nx * BK);
        cpa_commit();

        float* Acur = sm + (it % NSTG) * STG;
        float* Bcur = Acur + ASZ;

#pragma unroll
        for (int kk = 0; kk < BK; kk += 8) {
            wmma::fragment<wmma::matrix_a, 16, 16, 8, wmma::precision::tf32, wmma::row_major> af[FM];
#pragma unroll
            for (int i = 0; i < FM; i++)
                wmma::load_matrix_sync(af[i], &Acur[(wm * WM + i * 16) * AL + kk], AL);
            if (NT) {
                wmma::fragment<wmma::matrix_b, 16, 16, 8, wmma::precision::tf32, wmma::col_major> bf[FN];
#pragma unroll
                for (int j = 0; j < FN; j++)
                    wmma::load_matrix_sync(bf[j], &Bcur[(wn * WN + j * 16) * AL + kk], AL);
#pragma unroll
                for (int i = 0; i < FM; i++)
#pragma unroll
                    for (int j = 0; j < FN; j++)
                        wmma::mma_sync(acc[i][j], af[i], bf[j], acc[i][j]);
            } else {
                wmma::fragment<wmma::matrix_b, 16, 16, 8, wmma::precision::tf32, wmma::row_major> bf[FN];
#pragma unroll
                for (int j = 0; j < FN; j++)
                    wmma::load_matrix_sync(bf[j], &Bcur[kk * BLnn + wn * WN + j * 16], BLnn);
#pragma unroll
                for (int i = 0; i < FM; i++)
#pragma unroll
                    for (int j = 0; j < FN; j++)
                        wmma::mma_sync(acc[i][j], af[i], bf[j], acc[i][j]);
            }
        }
    }

#pragma unroll
    for (int i = 0; i < FM; i++)
#pragma unroll
        for (int j = 0; j < FN; j++) {
            if (RELU) {
#pragma unroll
                for (int t = 0; t < acc[i][j].num_elements; t++)
                    acc[i][j].x[t] = fmaxf(acc[i][j].x[t], 0.f);
            }
            wmma::store_matrix_sync(C + (long long)(wm * WM + i * 16) * ldc + wn * WN + j * 16,
                                    acc[i][j], ldc, wmma::mem_row_major);
        }
}

// ---------------- NN GEMM with split/batch dimension in blockIdx.z ----------------
template<int BM, int BN, int BK, int WM, int WN, int NWARP, int NSTG>
__global__ void __launch_bounds__(NWARP*32, 2) gemm_s(
    const float* __restrict__ Ag, const float* __restrict__ Bg, float* __restrict__ Cg,
    int K, int lda, int ldb, int ldc,
    long long sAb, long long sAh, long long sBb, long long sBh,
    long long sCb, long long sCh, int Hn, int nbh,
    long long sAs, long long sBs, long long sCs)
{
    constexpr int NTH  = NWARP * 32;
    constexpr int AL   = BK + 4;
    constexpr int BLnn = BN + 4;
    constexpr int ASZ  = BM * AL;
    constexpr int BSZ  = BK * BLnn;
    constexpr int STG  = ASZ + BSZ;
    constexpr int FM   = WM / 16;
    constexpr int FN   = WN / 16;
    constexpr int WROWS = BM / WM;

    extern __shared__ float sm[];

    int zz = blockIdx.z;
    int ss = zz / nbh, bh = zz - ss * nbh;
    int bb = bh / Hn, hh = bh - bb * Hn;
    const float* A  = Ag + (long long)ss * sAs + (long long)bb * sAb + (long long)hh * sAh
                         + (long long)(blockIdx.y * BM) * lda;
    const float* Bp = Bg + (long long)ss * sBs + (long long)bb * sBb + (long long)hh * sBh
                         + (long long)(blockIdx.x * BN);
    float*       C  = Cg + (long long)ss * sCs + (long long)bb * sCb + (long long)hh * sCh
                         + (long long)(blockIdx.y * BM) * ldc + blockIdx.x * BN;

    int tid = threadIdx.x;
    int wid = tid >> 5;
    int wm = wid % WROWS, wn = wid / WROWS;

    wmma::fragment<wmma::accumulator, 16, 16, 8, float> acc[FM][FN];
#pragma unroll
    for (int i = 0; i < FM; i++)
#pragma unroll
        for (int j = 0; j < FN; j++) wmma::fill_fragment(acc[i][j], 0.f);

    auto load_tile = [&](int s, int k0) {
        float* Ab = sm + s * STG;
        float* Bb = Ab + ASZ;
#pragma unroll
        for (int c = tid; c < BM * BK / 4; c += NTH) {
            int row = c / (BK / 4), c4 = c % (BK / 4);
            cpa16(&Ab[row * AL + c4 * 4], A + (long long)row * lda + k0 + c4 * 4);
        }
#pragma unroll
        for (int c = tid; c < BK * BN / 4; c += NTH) {
            int row = c / (BN / 4), c4 = c % (BN / 4);
            cpa16(&Bb[row * BLnn + c4 * 4], Bp + (long long)(k0 + row) * ldb + c4 * 4);
        }
    };

    int niter = K / BK;
    int pre = (niter < NSTG - 1) ? niter : NSTG - 1;
    for (int s = 0; s < pre; ++s) { load_tile(s, s * BK); cpa_commit(); }

    for (int it = 0; it < niter; ++it) {
        asm volatile("cp.async.wait_group %0;\n" :: "n"(NSTG - 2));
        __syncthreads();
        int nx = it + NSTG - 1;
        if (nx < niter) load_tile(nx % NSTG, nx * BK);
        cpa_commit();

        float* Acur = sm + (it % NSTG) * STG;
        float* Bcur = Acur + ASZ;

#pragma unroll
        for (int kk = 0; kk < BK; kk += 8) {
            wmma::fragment<wmma::matrix_a, 16, 16, 8, wmma::precision::tf32, wmma::row_major> af[FM];
#pragma unroll
            for (int i = 0; i < FM; i++)
                wmma::load_matrix_sync(af[i], &Acur[(wm * WM + i * 16) * AL + kk], AL);
            wmma::fragment<wmma::matrix_b, 16, 16, 8, wmma::precision::tf32, wmma::row_major> bf[FN];
#pragma unroll
            for (int j = 0; j < FN; j++)
                wmma::load_matrix_sync(bf[j], &Bcur[kk * BLnn + wn * WN + j * 16], BLnn);
#pragma unroll
            for (int i = 0; i < FM; i++)
#pragma unroll
                for (int j = 0; j < FN; j++)
                    wmma::mma_sync(acc[i][j], af[i], bf[j], acc[i][j]);
        }
    }

#pragma unroll
    for (int i = 0; i < FM; i++)
#pragma unroll
        for (int j = 0; j < FN; j++)
            wmma::store_matrix_sync(C + (long long)(wm * WM + i * 16) * ldc + wn * WN + j * 16,
                                    acc[i][j], ldc, wmma::mem_row_major);
}

// ---------------- fused attention: AC + shift/mask + softmax(no-max) + PV ----------------
// Grid (8, 32): block = (q-tile of 128 rows, batch*head). Streams K/V tiles of 128.
// S = qw@k^T (WMMA) ; P = exp((S + BD_raw[i, j+1023-i]) / 32) masked ; O += P@V ; O /= rowsum.
#define FA_LDQ 68
#define FA_LDS 132

__global__ void __launch_bounds__(256, 1) fused_attn_kernel()
{
    extern __shared__ float fsm[];
    float* q_sm = fsm;                    // 128*68
    float* k_sm = q_sm + 128*FA_LDQ;      // 128*68
    float* v_sm = k_sm + 128*FA_LDQ;      // 2 buffers * 128*68
    float* S_sm = v_sm + 2*128*FA_LDQ;    // 128*132
    float* l_sm = S_sm + 128*FA_LDS;      // 128
    float* lp_sm = l_sm + 128;            // 256

    int qy = 7 - blockIdx.x;              // long blocks first
    int bh = blockIdx.y;
    int bb = bh >> 4, hh = bh & 15;
    int i0 = qy * 128;
    int tid = threadIdx.x, wid = tid >> 5;
    int wm = wid & 3, wn = wid >> 2;      // 4x2 warp grid

    const float* qg  = g_qw + (size_t)bb*1048576 + (size_t)i0*1024 + hh*64;
    const float* kg  = g_k  + (size_t)bb*2097152 + hh*64;
    const float* vg  = g_v  + (size_t)bb*2097152 + hh*64;
    const float* bdg = g_bd + (size_t)bh*1024*2048;

    // q tile load (group 0)
#pragma unroll
    for (int c = tid; c < 128*16; c += 256) {
        int row = c >> 4, c4 = (c & 15) << 2;
        cpa16(&q_sm[row*FA_LDQ + c4], qg + (size_t)row*1024 + c4);
    }
    cpa_commit();
    if (tid < 128) l_sm[tid] = 0.f;

    int ntile = qy + 9;

    // preload k0, v0
#pragma unroll
    for (int c = tid; c < 128*16; c += 256) {
        int row = c >> 4, c4 = (c & 15) << 2;
        cpa16(&k_sm[row*FA_LDQ + c4], kg + (size_t)row*1024 + c4);
        cpa16(&v_sm[row*FA_LDQ + c4], vg + (size_t)row*1024 + c4);
    }
    cpa_commit();

    wmma::fragment<wmma::accumulator, 16, 16, 8, float> Oacc[2][2];
#pragma unroll
    for (int i = 0; i < 2; i++)
#pragma unroll
        for (int j = 0; j < 2; j++) wmma::fill_fragment(Oacc[i][j], 0.f);

    for (int kx = 0; kx < ntile; kx++) {
        int j0 = kx * 128;
        asm volatile("cp.async.wait_group 0;\n");
        __syncthreads();

        // --- S = qw @ k^T (128x128) ---
        wmma::fragment<wmma::accumulator, 16, 16, 8, float> sacc[2][4];
#pragma unroll
        for (int i = 0; i < 2; i++)
#pragma unroll
            for (int j = 0; j < 4; j++) wmma::fill_fragment(sacc[i][j], 0.f);
#pragma unroll
        for (int kk = 0; kk < 64; kk += 8) {
            wmma::fragment<wmma::matrix_a, 16, 16, 8, wmma::precision::tf32, wmma::row_major> af[2];
#pragma unroll
            for (int i = 0; i < 2; i++)
                wmma::load_matrix_sync(af[i], &q_sm[(wm*32 + i*16)*FA_LDQ + kk], FA_LDQ);
            wmma::fragment<wmma::matrix_b, 16, 16, 8, wmma::precision::tf32, wmma::col_major> bf[4];
#pragma unroll
            for (int j = 0; j < 4; j++)
                wmma::load_matrix_sync(bf[j], &k_sm[(wn*64 + j*16)*FA_LDQ + kk], FA_LDQ);
#pragma unroll
            for (int i = 0; i < 2; i++)
#pragma unroll
                for (int j = 0; j < 4; j++)
                    wmma::mma_sync(sacc[i][j], af[i], bf[j], sacc[i][j]);
        }
#pragma unroll
        for (int i = 0; i < 2; i++)
#pragma unroll
            for (int j = 0; j < 4; j++)
                wmma::store_matrix_sync(&S_sm[(wm*32 + i*16)*FA_LDS + wn*64 + j*16],
                                        sacc[i][j], FA_LDS, wmma::mem_row_major);
        __syncthreads();

        // prefetch next k and v (k_sm free after AC; v double-buffered)
        if (kx + 1 < ntile) {
            const float* kt = kg + (size_t)(j0 + 128)*1024;
            const float* vt = vg + (size_t)(j0 + 128)*1024;
            float* vb = v_sm + ((kx + 1) & 1) * 128*FA_LDQ;
#pragma unroll
            for (int c = tid; c < 128*16; c += 256) {
                int row = c >> 4, c4 = (c & 15) << 2;
                cpa16(&k_sm[row*FA_LDQ + c4], kt + (size_t)row*1024 + c4);
                cpa16(&vb[row*FA_LDQ + c4], vt + (size_t)row*1024 + c4);
            }
        }
        cpa_commit();

        // --- exp((S + BDshift)/32) with mask; row sums ---
        {
            int u = tid & 127, half = tid >> 7;
            int i = i0 + u;
            float* Srow = S_sm + u*FA_LDS + half*64;
            const float* bdr = bdg + (size_t)i*2048 + (j0 + 1023 - i) + half*64;
            int vmax = i + 1024 - j0 - half*64;   // local v2 <= vmax valid
            float rs = 0.f;
            if (vmax >= 63) {                      // fully valid fast path
#pragma unroll 4
                for (int v4 = 0; v4 < 64; v4 += 4) {
                    float4 s4 = *(float4*)(Srow + v4);
                    float p0 = __expf((s4.x + __ldg(bdr + v4 + 0)) * 0.03125f);
                    float p1 = __expf((s4.y + __ldg(bdr + v4 + 1)) * 0.03125f);
                    float p2 = __expf((s4.z + __ldg(bdr + v4 + 2)) * 0.03125f);
                    float p3 = __expf((s4.w + __ldg(bdr + v4 + 3)) * 0.03125f);
                    rs += (p0 + p1) + (p2 + p3);
                    *(float4*)(Srow + v4) = make_float4(p0, p1, p2, p3);
                }
            } else {
#pragma unroll 4
                for (int v4 = 0; v4 < 64; v4 += 4) {
                    float4 s4 = *(float4*)(Srow + v4);
                    float p0 = (v4+0 <= vmax) ? __expf((s4.x + __ldg(bdr + v4 + 0)) * 0.03125f) : 0.f;
                    float p1 = (v4+1 <= vmax) ? __expf((s4.y + __ldg(bdr + v4 + 1)) * 0.03125f) : 0.f;
                    float p2 = (v4+2 <= vmax) ? __expf((s4.z + __ldg(bdr + v4 + 2)) * 0.03125f) : 0.f;
                    float p3 = (v4+3 <= vmax) ? __expf((s4.w + __ldg(bdr + v4 + 3)) * 0.03125f) : 0.f;
                    rs += (p0 + p1) + (p2 + p3);
                    *(float4*)(Srow + v4) = make_float4(p0, p1, p2, p3);
                }
            }
            lp_sm[tid] = rs;
        }
        __syncthreads();
        if (tid < 128) l_sm[tid] += lp_sm[tid] + lp_sm[tid + 128];
        // no sync needed before PV for l (only S used); S writes synced above

        // --- O += P @ V (128x64) ---
        {
            float* vcur = v_sm + (kx & 1) * 128*FA_LDQ;
#pragma unroll
            for (int kk = 0; kk < 128; kk += 8) {
                wmma::fragment<wmma::matrix_a, 16, 16, 8, wmma::precision::tf32, wmma::row_major> paf[2];
#pragma unroll
                for (int i = 0; i < 2; i++)
                    wmma::load_matrix_sync(paf[i], &S_sm[(wm*32 + i*16)*FA_LDS + kk], FA_LDS);
                wmma::fragment<wmma::matrix_b, 16, 16, 8, wmma::precision::tf32, wmma::row_major> pbf[2];
#pragma unroll
                for (int j = 0; j < 2; j++)
                    wmma::load_matrix_sync(pbf[j], &vcur[kk*FA_LDQ + wn*32 + j*16], FA_LDQ);
#pragma unroll
                for (int i = 0; i < 2; i++)
#pragma unroll
                    for (int j = 0; j < 2; j++)
                        wmma::mma_sync(Oacc[i][j], paf[i], pbf[j], Oacc[i][j]);
            }
        }
        // next-iteration wait+sync protects S_sm reuse
    }

    __syncthreads();
    // stage O in S_sm, normalize rows, write out
#pragma unroll
    for (int i = 0; i < 2; i++)
#pragma unroll
        for (int j = 0; j < 2; j++)
            wmma::store_matrix_sync(&S_sm[(wm*32 + i*16)*FA_LDS + wn*32 + j*16],
                                    Oacc[i][j], FA_LDS, wmma::mem_row_major);
    __syncthreads();
    {
        int u = tid & 127, half = tid >> 7;
        float inv = 1.f / l_sm[u];
        float* og = g_o + (size_t)bb*1048576 + (size_t)(i0 + u)*1024 + hh*64 + half*32;
        const float* Orow = S_sm + u*FA_LDS + half*32;
#pragma unroll
        for (int d = 0; d < 32; d += 4) {
            float4 o4 = *(const float4*)(Orow + d);
            o4.x *= inv; o4.y *= inv; o4.z *= inv; o4.w *= inv;
            *(float4*)(og + d) = o4;
        }
    }
}

static const int FA_SMEM = (4*128*FA_LDQ + 128*FA_LDS + 128 + 256) * 4;  // ~208 KB

// ---------------- fused 3-input add + LayerNorm ----------------
__global__ void __launch_bounds__(256) add_ln3_kernel(
    const float* __restrict__ a, const float* __restrict__ b, const float* __restrict__ c,
    const float* __restrict__ gamma, const float* __restrict__ beta,
    float* __restrict__ out)
{
    int row = blockIdx.x, tid = threadIdx.x;
    __shared__ float sh[E_];
    __shared__ float red[256];
    size_t base = (size_t)row * E_;

    float s = 0.f;
    for (int col = tid; col < E_; col += 256) {
        float v = a[base + col] + b[base + col] + c[base + col];
        sh[col] = v; s += v;
    }
    red[tid] = s; __syncthreads();
    for (int st = 128; st; st >>= 1) { if (tid < st) red[tid] += red[tid + st]; __syncthreads(); }
    float mu = red[0] * (1.f / E_); __syncthreads();

    float vs = 0.f;
    for (int col = tid; col < E_; col += 256) { float d = sh[col] - mu; vs += d * d; }
    red[tid] = vs; __syncthreads();
    for (int st = 128; st; st >>= 1) { if (tid < st) red[tid] += red[tid + st]; __syncthreads(); }
    float rstd = rsqrtf(red[0] * (1.f / E_) + 1e-3f);

    for (int col = tid; col < E_; col += 256)
        out[base + col] = (sh[col] - mu) * rstd * gamma[col] + beta[col];
}

// ---------------- host ----------------
#define GEMM_S       gemm_s<128,128,16,64,64,4,4>
#define GEMM_NN_RELU gemm4<128,128,16,64,64,4,4,0,1>
#define GEMM_NT      gemm4<128,128,32,64,64,4,2,1,0>

static const int SZ_S   = 4 * (128*20 + 16*132) * 4;   // 74752
static const int SZ_NN  = 4 * (128*20 + 16*132) * 4;   // 74752
static const int SZ_NT  = 2 * (128*36 + 128*36) * 4;   // 73728

extern "C" void kernel_launch(void* const* d_in, const int* in_sizes, int n_in,
                              void* d_out, int out_size)
{
    const float* w      = (const float*)d_in[0];
    const float* r      = (const float*)d_in[1];
    const float* member = (const float*)d_in[2];
    const float* Wq  = (const float*)d_in[4];
    const float* Wk  = (const float*)d_in[5];
    const float* Wv  = (const float*)d_in[6];
    const float* Wr  = (const float*)d_in[7];
    const float* Wo  = (const float*)d_in[8];
    const float* rwb = (const float*)d_in[9];
    const float* rrb = (const float*)d_in[10];
    const float* ln1g = (const float*)d_in[11];
    const float* ln1b = (const float*)d_in[12];
    const float* W1  = (const float*)d_in[13];
    const float* W2  = (const float*)d_in[14];
    const float* ln2g = (const float*)d_in[15];
    const float* ln2b = (const float*)d_in[16];

    float *cat_, *q_, *qw_, *qr_, *k_, *v_, *rp_, *bd_, *o_, *x_, *h1_, *y_, *y2_;
    cudaGetSymbolAddress((void**)&cat_,  g_cat);
    cudaGetSymbolAddress((void**)&q_,    g_q);
    cudaGetSymbolAddress((void**)&qw_,   g_qw);
    cudaGetSymbolAddress((void**)&qr_,   g_qr);
    cudaGetSymbolAddress((void**)&k_,    g_k);
    cudaGetSymbolAddress((void**)&v_,    g_v);
    cudaGetSymbolAddress((void**)&rp_,   g_rp);
    cudaGetSymbolAddress((void**)&bd_,   g_bd);
    cudaGetSymbolAddress((void**)&o_,    g_o);
    cudaGetSymbolAddress((void**)&x_,    g_x);
    cudaGetSymbolAddress((void**)&h1_,   g_h1);
    cudaGetSymbolAddress((void**)&y_,    g_y);
    cudaGetSymbolAddress((void**)&y2_,   g_y2);

    cudaFuncSetAttribute(GEMM_S,       cudaFuncAttributeMaxDynamicSharedMemorySize, SZ_S);
    cudaFuncSetAttribute(GEMM_NN_RELU, cudaFuncAttributeMaxDynamicSharedMemorySize, SZ_NN);
    cudaFuncSetAttribute(GEMM_NT,      cudaFuncAttributeMaxDynamicSharedMemorySize, SZ_NT);
    cudaFuncSetAttribute(fused_attn_kernel, cudaFuncAttributeMaxDynamicSharedMemorySize, FA_SMEM);

    // 1) cat = concat(member, w)
    concat_kernel<<<4096, 256>>>((const float4*)member, (const float4*)w, (float4*)cat_);

    // 2a) merged {q = w@Wq, rp = r@Wr}
    GEMM_S<<<dim3(8, 16, 2), 128, SZ_S>>>(w, Wq, q_,
        1024, 1024, 1024, 1024,
        0,0,0,0,0,0, 1, 1,
        (long long)(r - w), (long long)(Wr - Wq), (long long)(rp_ - q_));

    // 2b) merged {k = cat@Wk, v = cat@Wv}
    GEMM_S<<<dim3(8, 32, 2), 128, SZ_S>>>(cat_, Wk, k_,
        1024, 1024, 1024, 1024,
        0,0,0,0,0,0, 1, 1,
        0LL, (long long)(Wv - Wk), (long long)(v_ - k_));

    // 3) biased q copies
    bias_add2_kernel<<<8192, 256>>>(q_, rwb, rrb, qw_, qr_, 2097152);

    // 4) BD_raw[b,h] = qr @ rp^T  (rp shared over batch)
    GEMM_NT<<<dim3(16, 8, 32), 128, SZ_NT>>>(qr_, rp_, bd_,
        64, 1024, 1024, 2048,
        1048576LL, 64LL, 0LL, 64LL, 33554432LL, 2097152LL, 16);

    // 5) fused attention: o = softmax((qw@k^T + shift(BD))/32) @ v
    fused_attn_kernel<<<dim3(8, 32), 256, FA_SMEM>>>();

    // 6) o @ Wo, split-K = 2 -> y, y2
    GEMM_S<<<dim3(8, 16, 2), 128, SZ_S>>>(o_, Wo, y_,
        512, 1024, 1024, 1024,
        0,0,0,0,0,0, 1, 1,
        512LL, 512LL*1024LL, (long long)(y2_ - y_));

    // 7) x = LN(w + y + y2)
    add_ln3_kernel<<<2048, 256>>>(w, y_, y2_, ln1g, ln1b, x_);

    // 8) h1 = relu(x @ W1)
    GEMM_NN_RELU<<<dim3(32, 16, 1), 128, SZ_NN>>>(x_, W1, h1_, 1024, 1024, 4096, 4096, 0,0,0,0,0,0, 1);

    // 9) h1 @ W2, split-K = 2 -> y, y2
    GEMM_S<<<dim3(8, 16, 2), 128, SZ_S>>>(h1_, W2, y_,
        2048, 4096, 1024, 1024,
        0,0,0,0,0,0, 1, 1,
        2048LL, 2048LL*1024LL, (long long)(y2_ - y_));

    // 10) out = LN(x + y + y2)
    add_ln3_kernel<<<2048, 256>>>(x_, y_, y2_, ln2g, ln2b, (float*)d_out);
}